// round 2
// baseline (speedup 1.0000x reference)
#include <cuda_runtime.h>

#define IMG 1024
#define NPIX (IMG*IMG)
#define NBLK 256          // persistent blocks; 2/SM * 148 SMs = 296 >= 256 -> barrier safe
#define RPB 4             // rows per block (256*4 = 1024)
#define SROW 1032         // smem row stride in floats (16B aligned, halo at idx 3 / 1028)

// Persistent state (allocation-free): h ping/pong/enc-final + decoder gate-base planes.
__device__ __align__(16) float g_h[3][NPIX];
__device__ __align__(16) float g_gb[4][NPIX];
__device__ unsigned g_bar;

// [0]=encoder, [1]=decoder. w flattened [o][ch][ky][kx] -> o*18+ch*9+ky*3+kx
__constant__ float c_w[2][72];
__constant__ float c_b[2][4];

__device__ __forceinline__ float sigf(float x){
    return __fdividef(1.0f, 1.0f + __expf(-x));            // 2 MUFU, ~1e-7 rel err
}
__device__ __forceinline__ float tanhf_fast(float x){
    return 2.0f * __fdividef(1.0f, 1.0f + __expf(-2.0f*x)) - 1.0f;
}

__global__ void bar_reset(){ g_bar = 0u; }

// Software grid barrier: monotonic counter, per-barrier target = k*NBLK.
__device__ __forceinline__ void gbar(int t, unsigned target){
    __syncthreads();
    if (t == 0){
        __threadfence();                       // release prior global writes
        atomicAdd(&g_bar, 1u);
        while (*((volatile unsigned*)&g_bar) < target) { }
        __threadfence();                       // order subsequent reads after spin
    }
    __syncthreads();
}

// Stage rows r0-1 .. r0+4 of a 1024x1024 plane into 6 smem rows (zero OOB + halo).
__device__ __forceinline__ void stage6(float* __restrict__ s,
                                       const float* __restrict__ g,
                                       int r0, int t){
    #pragma unroll
    for (int rr = 0; rr < 6; ++rr){
        int gy = r0 - 1 + rr;
        float4 v = make_float4(0.f, 0.f, 0.f, 0.f);
        if ((unsigned)gy < IMG) v = *(const float4*)(g + (size_t)gy*IMG + 4*t);
        *(float4*)(s + rr*SROW + 4 + 4*t) = v;
    }
    if (t < 12){
        int rr = t >> 1;
        s[rr*SROW + ((t & 1) ? 1028 : 3)] = 0.f;   // col -1 / col 1024 zeros
    }
}

// Accumulate 3x3 conv of one channel (smem-staged) into acc[4 gates][4 px].
// Wc points at c_w[sel] + ch*9 ; weight index o*18 + r*3 + k.
__device__ __forceinline__ void conv_ch(const float* __restrict__ s, int q, int col4,
                                        const float* __restrict__ Wc,
                                        float acc[4][4]){
    #pragma unroll
    for (int r = 0; r < 3; ++r){
        const float* srow = s + (q + r)*SROW;
        float  v0 = srow[col4 + 3];
        float4 vm = *(const float4*)(srow + col4 + 4);
        float  v5 = srow[col4 + 8];
        float v[6] = {v0, vm.x, vm.y, vm.z, vm.w, v5};
        #pragma unroll
        for (int o = 0; o < 4; ++o){
            const float w0 = Wc[o*18 + r*3 + 0];
            const float w1 = Wc[o*18 + r*3 + 1];
            const float w2 = Wc[o*18 + r*3 + 2];
            #pragma unroll
            for (int p = 0; p < 4; ++p)
                acc[o][p] = fmaf(v[p+2], w2,
                            fmaf(v[p+1], w1,
                            fmaf(v[p  ], w0, acc[o][p])));
        }
    }
}

__global__ __launch_bounds__(256, 2)
void convlstm_all(const float* __restrict__ data, float* __restrict__ out)
{
    extern __shared__ float smem[];
    float* sx = smem;              // 6*SROW floats
    float* sh = smem + 6*SROW;     // 6*SROW floats

    const int t    = threadIdx.x;
    const int r0   = blockIdx.x * RPB;
    const int col4 = 4 * t;

    float creg[16];                 // c state, 4 rows x 4 px, register-resident
    unsigned target = 0;

    // ======================= Encoder: 20 steps =======================
    #pragma unroll 1
    for (int step = 0; step < 20; ++step){
        const float* xg = data + (size_t)step * NPIX;
        stage6(sx, xg, r0, t);
        if (step > 0) stage6(sh, g_h[(step + 1) & 1], r0, t);
        __syncthreads();

        float* hout = g_h[step & 1];

        #pragma unroll
        for (int q = 0; q < RPB; ++q){
            float acc[4][4];
            #pragma unroll
            for (int o = 0; o < 4; ++o){
                const float bo = c_b[0][o];
                #pragma unroll
                for (int p = 0; p < 4; ++p) acc[o][p] = bo;
            }
            conv_ch(sx, q, col4, &c_w[0][0], acc);
            if (step > 0) conv_ch(sh, q, col4, &c_w[0][9], acc);

            const int base = (r0 + q) * IMG + col4;
            float hn[4];
            #pragma unroll
            for (int p = 0; p < 4; ++p){
                const float iv = sigf(acc[0][p]);
                const float fv = sigf(acc[1][p]);
                const float ov = sigf(acc[2][p]);
                const float gv = tanhf_fast(acc[3][p]);
                const float cold = (step == 0) ? 0.f : creg[q*4 + p];
                const float cn = fmaf(fv, cold, iv * gv);
                creg[q*4 + p] = cn;
                hn[p] = ov * tanhf_fast(cn);
            }
            *(float4*)(hout + base) = make_float4(hn[0], hn[1], hn[2], hn[3]);
        }
        target += NBLK;
        gbar(t, target);
    }
    // Final encoder h lives in g_h[1] (step 19 writes index 19&1 = 1).

    // ============ Decoder gate-base precompute (x = g_h[1], fixed) ============
    {
        stage6(sx, g_h[1], r0, t);
        __syncthreads();
        #pragma unroll
        for (int q = 0; q < RPB; ++q){
            float acc[4][4];
            #pragma unroll
            for (int o = 0; o < 4; ++o){
                const float bo = c_b[1][o];
                #pragma unroll
                for (int p = 0; p < 4; ++p) acc[o][p] = bo;
            }
            conv_ch(sx, q, col4, &c_w[1][0], acc);
            const int base = (r0 + q) * IMG + col4;
            #pragma unroll
            for (int o = 0; o < 4; ++o)
                *(float4*)(&g_gb[o][base]) =
                    make_float4(acc[o][0], acc[o][1], acc[o][2], acc[o][3]);
        }
        target += NBLK;
        gbar(t, target);
    }

    // ======================= Decoder: 20 steps =======================
    // h ping-pong: dbuf[0]=g_h[2], dbuf[1]=g_h[0]; step s writes dbuf[s&1].
    #pragma unroll 1
    for (int step = 0; step < 20; ++step){
        float* dbuf0 = g_h[2];
        float* dbuf1 = g_h[0];
        const float* hin = ((step & 1) == 0) ? dbuf1 : dbuf0;   // dbuf[(step+1)&1]
        float* hout = (step == 19) ? out
                     : (((step & 1) == 0) ? dbuf0 : dbuf1);

        if (step > 0) stage6(sh, hin, r0, t);
        __syncthreads();

        #pragma unroll
        for (int q = 0; q < RPB; ++q){
            const int base = (r0 + q) * IMG + col4;
            float acc[4][4];
            #pragma unroll
            for (int o = 0; o < 4; ++o){
                const float4 gb = *(const float4*)(&g_gb[o][base]);
                acc[o][0] = gb.x; acc[o][1] = gb.y; acc[o][2] = gb.z; acc[o][3] = gb.w;
            }
            if (step > 0) conv_ch(sh, q, col4, &c_w[1][9], acc);

            float hn[4];
            #pragma unroll
            for (int p = 0; p < 4; ++p){
                const float iv = sigf(acc[0][p]);
                const float fv = sigf(acc[1][p]);
                const float ov = sigf(acc[2][p]);
                const float gv = tanhf_fast(acc[3][p]);
                const float cold = (step == 0) ? 0.f : creg[q*4 + p];
                const float cn = fmaf(fv, cold, iv * gv);
                creg[q*4 + p] = cn;
                hn[p] = ov * tanhf_fast(cn);
            }
            *(float4*)(hout + base) = make_float4(hn[0], hn[1], hn[2], hn[3]);
        }
        if (step < 19){
            target += NBLK;
            gbar(t, target);
        }
    }
}

extern "C" void kernel_launch(void* const* d_in, const int* in_sizes, int n_in,
                              void* d_out, int out_size)
{
    (void)in_sizes; (void)n_in; (void)out_size;

    const float* data  = (const float*)d_in[0];   // [20,1,1,1024,1024]
    const float* enc_w = (const float*)d_in[1];   // [4,2,3,3]
    const float* enc_b = (const float*)d_in[2];   // [4]
    const float* dec_w = (const float*)d_in[3];
    const float* dec_b = (const float*)d_in[4];
    // d_in[5..7] = epoch(0), T_en(20), T_de(20): fixed by the problem; baked in.

    cudaMemcpyToSymbolAsync(c_w, enc_w, 72*sizeof(float), 0,
                            cudaMemcpyDeviceToDevice, 0);
    cudaMemcpyToSymbolAsync(c_w, dec_w, 72*sizeof(float), 72*sizeof(float),
                            cudaMemcpyDeviceToDevice, 0);
    cudaMemcpyToSymbolAsync(c_b, enc_b, 4*sizeof(float), 0,
                            cudaMemcpyDeviceToDevice, 0);
    cudaMemcpyToSymbolAsync(c_b, dec_b, 4*sizeof(float), 16,
                            cudaMemcpyDeviceToDevice, 0);

    const int smem_bytes = 12 * SROW * (int)sizeof(float);   // 49536
    cudaFuncSetAttribute(convlstm_all,
                         cudaFuncAttributeMaxDynamicSharedMemorySize, smem_bytes);

    bar_reset<<<1, 1>>>();
    convlstm_all<<<NBLK, 256, smem_bytes>>>(data, (float*)d_out);
}

// round 3
// speedup vs baseline: 1.0356x; 1.0356x over previous
#include <cuda_runtime.h>

#define IMG 1024
#define NPIX (IMG*IMG)
#define SROW 1032   // smem row stride (floats); data at [4..1027], halos at [3] and [1028]

typedef unsigned long long u64;

// Persistent scratch (allocation-free): h ping/pong/enc-final, c ping/pong,
// decoder gate-base planes, and staging for packed weights -> __constant__.
__device__ __align__(16) float g_h[3][NPIX];
__device__ __align__(16) float g_c[2][NPIX];
__device__ __align__(16) float g_gb[4][NPIX];
__device__ u64 g_wtmp[2][2][9][4];   // [sel][ch][r*3+k][gate], each = (w,w)
__device__ u64 g_btmp[2][4];         // (b,b)

__constant__ u64 c_w2[2][2][9][4];
__constant__ u64 c_b2[2][4];

// ---------------- f32x2 helpers ----------------
__device__ __forceinline__ u64 ffma2(u64 a, u64 b, u64 c){
    u64 d; asm("fma.rn.f32x2 %0, %1, %2, %3;" : "=l"(d) : "l"(a), "l"(b), "l"(c));
    return d;
}
__device__ __forceinline__ u64 pk2(float lo, float hi){
    u64 r; asm("mov.b64 %0, {%1, %2};" : "=l"(r) : "f"(lo), "f"(hi)); return r;
}
__device__ __forceinline__ void unpk(u64 v, float& a, float& b){
    asm("mov.b64 {%0, %1}, %2;" : "=f"(a), "=f"(b) : "l"(v));
}

__device__ __forceinline__ float sigf(float x){
    return __fdividef(1.0f, 1.0f + __expf(-x));          // 2 MUFU, ~1e-7 err
}
__device__ __forceinline__ float tanhf_fast(float x){
    return 2.0f * __fdividef(1.0f, 1.0f + __expf(-2.0f*x)) - 1.0f;
}

// Pack weights (w,w) into staging buffers; copied to __constant__ afterwards.
__global__ void pack_weights(const float* __restrict__ ew, const float* __restrict__ eb,
                             const float* __restrict__ dw, const float* __restrict__ db)
{
    int i = threadIdx.x;
    if (i < 72){
        int o = i / 18, ch = (i % 18) / 9, j = i % 9;   // src: o*18 + ch*9 + j
        u64 ue = (u64)__float_as_uint(ew[i]); g_wtmp[0][ch][j][o] = ue | (ue << 32);
        u64 ud = (u64)__float_as_uint(dw[i]); g_wtmp[1][ch][j][o] = ud | (ud << 32);
    }
    if (i < 4){
        u64 ue = (u64)__float_as_uint(eb[i]); g_btmp[0][i] = ue | (ue << 32);
        u64 ud = (u64)__float_as_uint(db[i]); g_btmp[1][i] = ud | (ud << 32);
    }
}

// Stage rows row-1..row+1 of a plane into 3 smem rows (zero OOB + side halos).
__device__ __forceinline__ void stage3(float* __restrict__ s,
                                       const float* __restrict__ g,
                                       int row, int t)
{
    #pragma unroll
    for (int rr = 0; rr < 3; ++rr){
        int gy = row - 1 + rr;
        float4 v = make_float4(0.f, 0.f, 0.f, 0.f);
        if ((unsigned)gy < IMG) v = *(const float4*)(g + (size_t)gy*IMG + 4*t);
        *(float4*)(s + rr*SROW + 4 + 4*t) = v;
    }
    if (t < 6) s[(t >> 1)*SROW + ((t & 1) ? 1028 : 3)] = 0.f;
}

// 3x3 conv of one channel into packed acc[gate][pxpair] via f32x2 FMA.
// W = c_w2[sel][ch] -> [9][4] duplicated weights.
__device__ __forceinline__ void conv_ch2(const float* __restrict__ sp, int col4,
                                         const u64 (*__restrict__ W)[4],
                                         u64 acc[4][2])
{
    #pragma unroll
    for (int r = 0; r < 3; ++r){
        const float* srow = sp + r*SROW;
        float v0 = srow[col4 + 3];
        u64 p12  = *(const u64*)(srow + col4 + 4);   // (v1,v2), 8B aligned
        u64 p34  = *(const u64*)(srow + col4 + 6);   // (v3,v4), 8B aligned
        float v5 = srow[col4 + 8];
        float v1, v2, v3, v4;
        unpk(p12, v1, v2); unpk(p34, v3, v4);
        const u64 A = pk2(v0, v1);     // (v0,v1)
        const u64 C = pk2(v2, v3);     // (v2,v3)
        const u64 E = pk2(v4, v5);     // (v4,v5)
        #pragma unroll
        for (int o = 0; o < 4; ++o){
            const u64 w0 = W[r*3 + 0][o];
            const u64 w1 = W[r*3 + 1][o];
            const u64 w2 = W[r*3 + 2][o];
            acc[o][0] = ffma2(A,   w0, acc[o][0]);
            acc[o][0] = ffma2(p12, w1, acc[o][0]);
            acc[o][0] = ffma2(C,   w2, acc[o][0]);
            acc[o][1] = ffma2(C,   w0, acc[o][1]);
            acc[o][1] = ffma2(p34, w1, acc[o][1]);
            acc[o][1] = ffma2(E,   w2, acc[o][1]);
        }
    }
}

// One ConvLSTM step. ENC: gates = conv(x)+conv(h)+b. DEC: gates = gbase+conv(h)
// (gbase = conv(enc_final)+b precomputed). FIRST: h=c=0.
template<bool ENC, bool FIRST>
__global__ __launch_bounds__(256, 3)
void lstm_step(const float* __restrict__ xin,
               const float* __restrict__ hprev,
               const float* __restrict__ cprev,
               float* __restrict__ hout,
               float* __restrict__ cout)
{
    __shared__ __align__(16) float s[2][3][SROW];

    const int t = threadIdx.x;
    const int row = blockIdx.x;
    const int col4 = 4 * t;
    const int base = row * IMG + col4;
    constexpr int sel = ENC ? 0 : 1;

    if (ENC)    stage3(&s[0][0][0], xin,   row, t);
    if (!FIRST) stage3(&s[1][0][0], hprev, row, t);
    __syncthreads();

    u64 acc[4][2];
    if (ENC){
        #pragma unroll
        for (int o = 0; o < 4; ++o){ acc[o][0] = c_b2[0][o]; acc[o][1] = c_b2[0][o]; }
        conv_ch2(&s[0][0][0], col4, c_w2[0][0], acc);
        if (!FIRST) conv_ch2(&s[1][0][0], col4, c_w2[0][1], acc);
    } else {
        #pragma unroll
        for (int o = 0; o < 4; ++o){
            const ulonglong2 gb = *(const ulonglong2*)(&g_gb[o][base]);
            acc[o][0] = gb.x; acc[o][1] = gb.y;
        }
        if (!FIRST) conv_ch2(&s[1][0][0], col4, c_w2[sel][1], acc);
    }

    float gi[4], gf[4], go[4], gg[4];
    unpk(acc[0][0], gi[0], gi[1]); unpk(acc[0][1], gi[2], gi[3]);
    unpk(acc[1][0], gf[0], gf[1]); unpk(acc[1][1], gf[2], gf[3]);
    unpk(acc[2][0], go[0], go[1]); unpk(acc[2][1], go[2], go[3]);
    unpk(acc[3][0], gg[0], gg[1]); unpk(acc[3][1], gg[2], gg[3]);

    float cold[4] = {0.f, 0.f, 0.f, 0.f};
    if (!FIRST){
        float4 cp = *(const float4*)(cprev + base);
        cold[0] = cp.x; cold[1] = cp.y; cold[2] = cp.z; cold[3] = cp.w;
    }

    float hn[4], cn[4];
    #pragma unroll
    for (int p = 0; p < 4; ++p){
        const float iv = sigf(gi[p]);
        const float fv = sigf(gf[p]);
        const float ov = sigf(go[p]);
        const float gv = tanhf_fast(gg[p]);
        const float c2 = FIRST ? (iv * gv) : fmaf(fv, cold[p], iv * gv);
        cn[p] = c2;
        hn[p] = ov * tanhf_fast(c2);
    }

    *(float4*)(cout + base) = make_float4(cn[0], cn[1], cn[2], cn[3]);
    *(float4*)(hout + base) = make_float4(hn[0], hn[1], hn[2], hn[3]);
}

// Decoder gate-base: gbase[o] = conv3x3(enc_final, dec_w[ch0]) + dec_b, once.
__global__ __launch_bounds__(256, 3)
void gbase_compute(const float* __restrict__ hfin)
{
    __shared__ __align__(16) float s[3][SROW];
    const int t = threadIdx.x;
    const int row = blockIdx.x;
    const int col4 = 4 * t;
    const int base = row * IMG + col4;

    stage3(&s[0][0], hfin, row, t);
    __syncthreads();

    u64 acc[4][2];
    #pragma unroll
    for (int o = 0; o < 4; ++o){ acc[o][0] = c_b2[1][o]; acc[o][1] = c_b2[1][o]; }
    conv_ch2(&s[0][0], col4, c_w2[1][0], acc);

    #pragma unroll
    for (int o = 0; o < 4; ++o){
        ulonglong2 v; v.x = acc[o][0]; v.y = acc[o][1];
        *(ulonglong2*)(&g_gb[o][base]) = v;
    }
}

extern "C" void kernel_launch(void* const* d_in, const int* in_sizes, int n_in,
                              void* d_out, int out_size)
{
    (void)in_sizes; (void)n_in; (void)out_size;

    const float* data  = (const float*)d_in[0];   // [20,1,1,1024,1024]
    const float* enc_w = (const float*)d_in[1];   // [4,2,3,3]
    const float* enc_b = (const float*)d_in[2];   // [4]
    const float* dec_w = (const float*)d_in[3];
    const float* dec_b = (const float*)d_in[4];
    // d_in[5..7] = epoch(0), T_en(20), T_de(20): fixed by the problem; baked in.

    // Pack (w,w) pairs on device, then copy into constant bank (all capturable).
    pack_weights<<<1, 128>>>(enc_w, enc_b, dec_w, dec_b);
    void* pw; void* pb;
    cudaGetSymbolAddress(&pw, g_wtmp);
    cudaGetSymbolAddress(&pb, g_btmp);
    cudaMemcpyToSymbolAsync(c_w2, pw, sizeof(g_wtmp), 0, cudaMemcpyDeviceToDevice, 0);
    cudaMemcpyToSymbolAsync(c_b2, pb, sizeof(g_btmp), 0, cudaMemcpyDeviceToDevice, 0);

    void *ph, *pc;
    cudaGetSymbolAddress(&ph, g_h);
    cudaGetSymbolAddress(&pc, g_c);
    float* H0 = (float*)ph;
    float* H1 = H0 + NPIX;
    float* H2 = H0 + 2*NPIX;
    float* C0 = (float*)pc;
    float* C1 = C0 + NPIX;

    const dim3 grid(IMG), block(256);

    // ---------------- Encoder: 20 steps ----------------
    // step s: h out = g_h[s&1], h in = g_h[(s+1)&1]; c likewise.
    lstm_step<true, true><<<grid, block>>>(data, nullptr, nullptr, H0, C0);
    for (int s = 1; s < 20; ++s){
        const float* xf = data + (size_t)s * NPIX;
        float* hin  = (s & 1) ? H0 : H1;
        float* hout = (s & 1) ? H1 : H0;
        float* cin  = (s & 1) ? C0 : C1;
        float* cout = (s & 1) ? C1 : C0;
        lstm_step<true, false><<<grid, block>>>(xf, hin, cin, hout, cout);
    }
    // Encoder final h in H1 (step 19).

    gbase_compute<<<grid, block>>>(H1);

    // ---------------- Decoder: 20 steps ----------------
    // h ping-pong dh = {H2, H0}; step s writes dh[s&1] (s=19 -> out).
    lstm_step<false, true><<<grid, block>>>(nullptr, nullptr, nullptr, H2, C0);
    for (int s = 1; s < 20; ++s){
        float* hin  = (s & 1) ? H2 : H0;
        float* hout = (s & 1) ? H0 : H2;
        float* cin  = (s & 1) ? C0 : C1;
        float* cout = (s & 1) ? C1 : C0;
        if (s == 19) hout = (float*)d_out;
        lstm_step<false, false><<<grid, block>>>(nullptr, hin, cin, hout, cout);
    }
}

// round 4
// speedup vs baseline: 1.0663x; 1.0297x over previous
#include <cuda_runtime.h>

#define IMG 1024
#define NPIX (IMG*IMG)

typedef unsigned long long u64;

// Persistent scratch (allocation-free): h ping/pong/enc-final, c ping/pong,
// decoder gate-base planes, weight-packing staging.
__device__ __align__(16) float g_h[3][NPIX];
__device__ __align__(16) float g_c[2][NPIX];
__device__ __align__(16) float g_gb[4][NPIX];
__device__ u64 g_wtmp[2][2][9][4];   // [sel][ch][r*3+k][gate] = (w,w)
__device__ u64 g_btmp[2][4];         // (b,b)

__constant__ u64 c_w2[2][2][9][4];
__constant__ u64 c_b2[2][4];

// ---------------- f32x2 helpers ----------------
__device__ __forceinline__ u64 ffma2(u64 a, u64 b, u64 c){
    u64 d; asm("fma.rn.f32x2 %0, %1, %2, %3;" : "=l"(d) : "l"(a), "l"(b), "l"(c));
    return d;
}
__device__ __forceinline__ u64 pk2(float lo, float hi){
    u64 r; asm("mov.b64 %0, {%1, %2};" : "=l"(r) : "f"(lo), "f"(hi)); return r;
}
__device__ __forceinline__ void unpk(u64 v, float& a, float& b){
    asm("mov.b64 {%0, %1}, %2;" : "=f"(a), "=f"(b) : "l"(v));
}

__device__ __forceinline__ float sigf(float x){
    return __fdividef(1.0f, 1.0f + __expf(-x));          // EX2+RCP, ~1e-7 err
}
__device__ __forceinline__ float tanhf_fast(float x){
    return 2.0f * __fdividef(1.0f, 1.0f + __expf(-2.0f*x)) - 1.0f;
}

// Pack (w,w) pairs on device; copied to __constant__ afterwards.
__global__ void pack_weights(const float* __restrict__ ew, const float* __restrict__ eb,
                             const float* __restrict__ dw, const float* __restrict__ db)
{
    int i = threadIdx.x;
    if (i < 72){
        int o = i / 18, ch = (i % 18) / 9, j = i % 9;   // src: o*18 + ch*9 + j
        u64 ue = (u64)__float_as_uint(ew[i]); g_wtmp[0][ch][j][o] = ue | (ue << 32);
        u64 ud = (u64)__float_as_uint(dw[i]); g_wtmp[1][ch][j][o] = ud | (ud << 32);
    }
    if (i < 4){
        u64 ue = (u64)__float_as_uint(eb[i]); g_btmp[0][i] = ue | (ue << 32);
        u64 ud = (u64)__float_as_uint(db[i]); g_btmp[1][i] = ud | (ud << 32);
    }
}

// One conv row (one channel, one kernel row) accumulated straight from global.
// Thread t covers output cols 4t..4t+3; taps need cols 4t-1..4t+4 of row gy.
// Wr = 3 taps x 4 gates of duplicated weights.
__device__ __forceinline__ void conv_row2(const float* __restrict__ plane, int gy, int t,
                                          const u64 (*__restrict__ Wr)[4],
                                          u64 acc[4][2])
{
    u64 A, B, C, D, E;
    if ((unsigned)gy < IMG){
        const float* r = plane + (size_t)gy*IMG + 4*t;
        float2 a = *(const float2*)(r);        // v1,v2  (16B-aligned addr)
        float2 b = *(const float2*)(r + 2);    // v3,v4  (8B-aligned addr)
        float v0 = (t > 0)   ? r[-1] : 0.f;
        float v5 = (t < 255) ? r[4]  : 0.f;
        A = pk2(v0,  a.x);
        B = pk2(a.x, a.y);   // = loaded pair, free
        C = pk2(a.y, b.x);
        D = pk2(b.x, b.y);   // = loaded pair, free
        E = pk2(b.y, v5);
    } else {
        A = B = C = D = E = 0ull;
    }
    #pragma unroll
    for (int o = 0; o < 4; ++o){
        const u64 w0 = Wr[0][o], w1 = Wr[1][o], w2 = Wr[2][o];
        acc[o][0] = ffma2(A, w0, acc[o][0]);
        acc[o][0] = ffma2(B, w1, acc[o][0]);
        acc[o][0] = ffma2(C, w2, acc[o][0]);
        acc[o][1] = ffma2(C, w0, acc[o][1]);
        acc[o][1] = ffma2(D, w1, acc[o][1]);
        acc[o][1] = ffma2(E, w2, acc[o][1]);
    }
}

// One ConvLSTM step, no smem. ENC: gates = conv(x)+conv(h)+b.
// DEC: gates = gbase + conv(h)  (gbase = conv(enc_final)+b precomputed).
// FIRST: h = c = 0.
template<bool ENC, bool FIRST>
__global__ __launch_bounds__(256, 4)
void lstm_step(const float* __restrict__ xin,
               const float* __restrict__ hprev,
               const float* __restrict__ cprev,
               float* __restrict__ hout,
               float* __restrict__ cout)
{
    const int t    = threadIdx.x;
    const int row  = blockIdx.x;
    const int base = row * IMG + 4*t;
    constexpr int sel = ENC ? 0 : 1;

    // c load issued early (independent of conv)
    float4 cp = make_float4(0.f, 0.f, 0.f, 0.f);
    if (!FIRST) cp = *(const float4*)(cprev + base);

    u64 acc[4][2];
    if (ENC){
        #pragma unroll
        for (int o = 0; o < 4; ++o){ acc[o][0] = c_b2[0][o]; acc[o][1] = c_b2[0][o]; }
        #pragma unroll
        for (int r = 0; r < 3; ++r)
            conv_row2(xin, row - 1 + r, t, &c_w2[0][0][r*3], acc);
    } else {
        #pragma unroll
        for (int o = 0; o < 4; ++o){
            const ulonglong2 gb = *(const ulonglong2*)(&g_gb[o][base]);
            acc[o][0] = gb.x; acc[o][1] = gb.y;
        }
    }
    if (!FIRST){
        #pragma unroll
        for (int r = 0; r < 3; ++r)
            conv_row2(hprev, row - 1 + r, t, &c_w2[sel][1][r*3], acc);
    }

    float gi[4], gf[4], go[4], gg[4];
    unpk(acc[0][0], gi[0], gi[1]); unpk(acc[0][1], gi[2], gi[3]);
    unpk(acc[1][0], gf[0], gf[1]); unpk(acc[1][1], gf[2], gf[3]);
    unpk(acc[2][0], go[0], go[1]); unpk(acc[2][1], go[2], go[3]);
    unpk(acc[3][0], gg[0], gg[1]); unpk(acc[3][1], gg[2], gg[3]);

    const float cold[4] = {cp.x, cp.y, cp.z, cp.w};

    float hn[4], cn[4];
    #pragma unroll
    for (int p = 0; p < 4; ++p){
        const float iv = sigf(gi[p]);
        const float fv = sigf(gf[p]);
        const float ov = sigf(go[p]);
        const float gv = tanhf_fast(gg[p]);
        const float c2 = FIRST ? (iv * gv) : fmaf(fv, cold[p], iv * gv);
        cn[p] = c2;
        hn[p] = ov * tanhf_fast(c2);
    }

    *(float4*)(cout + base) = make_float4(cn[0], cn[1], cn[2], cn[3]);
    *(float4*)(hout + base) = make_float4(hn[0], hn[1], hn[2], hn[3]);
}

// Decoder gate-base: gbase[o] = conv3x3(enc_final, dec_w[ch0]) + dec_b, once.
__global__ __launch_bounds__(256, 4)
void gbase_compute(const float* __restrict__ hfin)
{
    const int t    = threadIdx.x;
    const int row  = blockIdx.x;
    const int base = row * IMG + 4*t;

    u64 acc[4][2];
    #pragma unroll
    for (int o = 0; o < 4; ++o){ acc[o][0] = c_b2[1][o]; acc[o][1] = c_b2[1][o]; }
    #pragma unroll
    for (int r = 0; r < 3; ++r)
        conv_row2(hfin, row - 1 + r, t, &c_w2[1][0][r*3], acc);

    #pragma unroll
    for (int o = 0; o < 4; ++o){
        ulonglong2 v; v.x = acc[o][0]; v.y = acc[o][1];
        *(ulonglong2*)(&g_gb[o][base]) = v;
    }
}

extern "C" void kernel_launch(void* const* d_in, const int* in_sizes, int n_in,
                              void* d_out, int out_size)
{
    (void)in_sizes; (void)n_in; (void)out_size;

    const float* data  = (const float*)d_in[0];   // [20,1,1,1024,1024]
    const float* enc_w = (const float*)d_in[1];   // [4,2,3,3]
    const float* enc_b = (const float*)d_in[2];   // [4]
    const float* dec_w = (const float*)d_in[3];
    const float* dec_b = (const float*)d_in[4];
    // d_in[5..7] = epoch(0), T_en(20), T_de(20): fixed; baked in.

    pack_weights<<<1, 128>>>(enc_w, enc_b, dec_w, dec_b);
    void* pw; void* pb;
    cudaGetSymbolAddress(&pw, g_wtmp);
    cudaGetSymbolAddress(&pb, g_btmp);
    cudaMemcpyToSymbolAsync(c_w2, pw, sizeof(g_wtmp), 0, cudaMemcpyDeviceToDevice, 0);
    cudaMemcpyToSymbolAsync(c_b2, pb, sizeof(g_btmp), 0, cudaMemcpyDeviceToDevice, 0);

    void *ph, *pc;
    cudaGetSymbolAddress(&ph, g_h);
    cudaGetSymbolAddress(&pc, g_c);
    float* H0 = (float*)ph;
    float* H1 = H0 + NPIX;
    float* H2 = H0 + 2*NPIX;
    float* C0 = (float*)pc;
    float* C1 = C0 + NPIX;

    const dim3 grid(IMG), block(256);

    // ---------------- Encoder: 20 steps ----------------
    lstm_step<true, true><<<grid, block>>>(data, nullptr, nullptr, H0, C0);
    for (int s = 1; s < 20; ++s){
        const float* xf = data + (size_t)s * NPIX;
        float* hin  = (s & 1) ? H0 : H1;
        float* hout = (s & 1) ? H1 : H0;
        float* cin  = (s & 1) ? C0 : C1;
        float* cout = (s & 1) ? C1 : C0;
        lstm_step<true, false><<<grid, block>>>(xf, hin, cin, hout, cout);
    }
    // Encoder final h in H1 (step 19).

    gbase_compute<<<grid, block>>>(H1);

    // ---------------- Decoder: 20 steps ----------------
    lstm_step<false, true><<<grid, block>>>(nullptr, nullptr, nullptr, H2, C0);
    for (int s = 1; s < 20; ++s){
        float* hin  = (s & 1) ? H2 : H0;
        float* hout = (s & 1) ? H0 : H2;
        float* cin  = (s & 1) ? C0 : C1;
        float* cout = (s & 1) ? C1 : C0;
        if (s == 19) hout = (float*)d_out;
        lstm_step<false, false><<<grid, block>>>(nullptr, hin, cin, hout, cout);
    }
}